// round 8
// baseline (speedup 1.0000x reference)
#include <cuda_runtime.h>
#include <math.h>

#define B_    32
#define NCH   1024
#define NPTS  4096
#define NBK   256        // radius buckets
#define NCHK  256        // 16-pt chunks per batch

__device__ int    g_imp[B_ * NCH];               // winner per (b, c)
__device__ float4 g_sorted[B_ * NPTS];           // (x,y,z, r_ub|idx12) desc-r
__device__ float  g_chunkub[B_ * NCHK];          // suffix max of r_ub per chunk

// ---------------------------------------------------------------------------
// Kernel 0: per-batch prep. Computes radii, bucket-sorts points descending,
// packs orig idx into low 12 mantissa bits of an upward-rounded radius,
// builds per-chunk suffix UBs. Also writes the x passthrough.
// grid = 32, 1024 threads.
// ---------------------------------------------------------------------------
__global__ void __launch_bounds__(1024) prep_kernel(
    const float* __restrict__ x, float* __restrict__ out_x)
{
    __shared__ int   hist[NBK];
    __shared__ int   sbase[NBK];
    __shared__ int   cur[NBK];
    __shared__ float ub[NCHK];

    const int b    = blockIdx.x;
    const int t    = threadIdx.x;
    const int lane = t & 31;
    const int wid  = t >> 5;

    if (t < NBK) { hist[t] = 0; cur[t] = 0; }
    __syncthreads();

    const float* x0 = x + (size_t)b * 3 * NPTS;
    const float* x1 = x0 + NPTS;
    const float* x2 = x0 + 2 * NPTS;
    float*       o0 = out_x + (size_t)b * 3 * NPTS;

    float ax[4], ay[4], az[4], rr[4];
    int   bk[4];
    #pragma unroll
    for (int k = 0; k < 4; ++k) {
        int p = t + k * 1024;
        float a = x0[p], c = x1[p], d = x2[p];
        o0[p] = a; o0[NPTS + p] = c; o0[2 * NPTS + p] = d;   // passthrough
        float r2 = __fmaf_rn(a, a, __fmaf_rn(c, c, d * d));
        float r  = __fsqrt_ru(r2);
        ax[k] = a; ay[k] = c; az[k] = d; rr[k] = r;
        int bb = (int)(r * 40.0f);
        bk[k] = bb > 255 ? 255 : bb;
        atomicAdd(&hist[bk[k]], 1);
    }
    __syncthreads();

    // exclusive offsets in DESCENDING bucket order (warp 0)
    if (wid == 0) {
        int carry = 0;
        #pragma unroll
        for (int seg = 0; seg < 8; ++seg) {
            int idx = 255 - (seg * 32 + lane);
            int v = hist[idx];
            int s = v;
            #pragma unroll
            for (int off = 1; off < 32; off <<= 1) {
                int u = __shfl_up_sync(0xffffffffu, s, off);
                if (lane >= off) s += u;
            }
            sbase[idx] = s - v + carry;
            carry += __shfl_sync(0xffffffffu, s, 31);
        }
    }
    __syncthreads();

    // scatter: pack idx into low 12 bits of r, rounded UP (+0x1000 keeps low12)
    #pragma unroll
    for (int k = 0; k < 4; ++k) {
        int p = t + k * 1024;
        unsigned u = __float_as_uint(rr[k]);
        float rpk = __uint_as_float(((u & ~0xFFFu) | (unsigned)p) + 0x1000u);
        int pos = sbase[bk[k]] + atomicAdd(&cur[bk[k]], 1);
        g_sorted[(size_t)b * NPTS + pos] = make_float4(ax[k], ay[k], az[k], rpk);
    }
    __threadfence_block();
    __syncthreads();

    // per-chunk max then suffix max (descending positions)
    if (t < NCHK) {
        const float4* sp = g_sorted + (size_t)b * NPTS + t * 16;
        float m = 0.0f;
        #pragma unroll
        for (int i = 0; i < 16; ++i) m = fmaxf(m, sp[i].w);
        ub[t] = m;
    }
    __syncthreads();
    if (wid == 0) {
        float carry = 0.0f;
        #pragma unroll
        for (int seg = 0; seg < 8; ++seg) {
            int idx = 255 - (seg * 32 + lane);
            float v = ub[idx];
            float s = v;
            #pragma unroll
            for (int off = 1; off < 32; off <<= 1) {
                float u = __shfl_up_sync(0xffffffffu, s, off);
                if (lane >= off) s = fmaxf(s, u);
            }
            g_chunkub[b * NCHK + idx] = fmaxf(s, carry);
            carry = fmaxf(carry, __shfl_sync(0xffffffffu, s, 31));
        }
    }
}

// ---------------------------------------------------------------------------
// Kernel 1: pruned argmax. Thread = channel. Scans desc-radius points;
// skips points with |w|*r < best (safe), exits when chunk suffix-UB fails
// for the whole warp. Exact: slack factor covers all fp rounding.
// grid = 128 (32 b x 4 grp), 256 threads.
// ---------------------------------------------------------------------------
__global__ void __launch_bounds__(256) argmax_kernel(const float* __restrict__ W)
{
    const int b   = blockIdx.x >> 2;
    const int grp = blockIdx.x & 3;
    const int c   = grp * 256 + threadIdx.x;

    const float w0 = W[c * 3 + 0];
    const float w1 = W[c * 3 + 1];
    const float w2 = W[c * 3 + 2];
    const float wn = __fsqrt_ru(__fmaf_ru(w0, w0, __fmaf_ru(w1, w1, w1 * 0.0f + w2 * w2)))
                     * 1.00002f;

    const float4* sp  = g_sorted  + (size_t)b * NPTS;
    const float*  cub = g_chunkub + b * NCHK;

    float best = -INFINITY;
    int   bidx = 0;

    #pragma unroll 1
    for (int ck = 0; ck < NCHK; ++ck) {
        const float4* base = sp + ck * 16;
        #pragma unroll
        for (int i = 0; i < 16; ++i) {
            float4 p = base[i];                      // broadcast LDG (L1-hot)
            if (p.w * wn >= best) {
                float f = __fmaf_rn(w2, p.z, __fmaf_rn(w1, p.y, __fmul_rn(w0, p.x)));
                int idx = (int)(__float_as_uint(p.w) & 0xFFFu);
                if (f > best)            { best = f; bidx = idx; }
                else if (f == best && idx < bidx) bidx = idx;
            }
        }
        if (ck + 1 < NCHK) {
            float u = cub[ck + 1];
            if (!__ballot_sync(0xffffffffu, u * wn >= best)) break;
        }
    }
    g_imp[b * NCH + c] = bidx;
}

// ---------------------------------------------------------------------------
// Kernel 2: counts, entropy, parallel stable counting sort (R5-proven layout).
// grid = 32, 1024 threads, 63.5KB dynamic smem.
// ---------------------------------------------------------------------------
__global__ void __launch_bounds__(1024) sort_entropy_kernel(
    float* __restrict__ out_counts,
    float* __restrict__ out_imp2,
    float* __restrict__ out_ent)
{
    extern __shared__ __align__(16) char smem_raw[];
    int*            scnt   = (int*)smem_raw;                       // 16384 B
    int*            gstart = (int*)(smem_raw + 16384);             // 1025 ints
    unsigned short* chh    = (unsigned short*)(smem_raw + 20488);  // 1025*17 u16
    unsigned short* lrk    = (unsigned short*)(smem_raw + 55340);  // 4096 u16
    __shared__ float red[32];
    __shared__ int   ired[32];

    const int b    = blockIdx.x;
    const int t    = threadIdx.x;
    const int lane = t & 31;
    const int wid  = t >> 5;

    // prefetch winner idx before zeroing hides LDG latency
    const int myimp = g_imp[b * NCH + t];

    #pragma unroll
    for (int i = t; i < NPTS; i += 1024) scnt[i] = 0;
    for (int i = t; i < 8713; i += 1024) ((unsigned*)chh)[i] = 0;
    __syncthreads();

    atomicAdd(&scnt[myimp], 1);
    __syncthreads();

    // counts (float4) + entropy partial (sum analytically = 1024 + 4096e-6)
    const float inv_s = 1.0f / (1024.0f + 4096.0f * 1e-6f);
    float part2;
    {
        int4 cv = ((const int4*)scnt)[t];
        float4 cf = make_float4((float)cv.x, (float)cv.y, (float)cv.z, (float)cv.w);
        ((float4*)(out_counts + (size_t)b * NPTS))[t] = cf;
        float p0 = (cf.x + 1e-6f) * inv_s, p1 = (cf.y + 1e-6f) * inv_s;
        float p2 = (cf.z + 1e-6f) * inv_s, p3 = (cf.w + 1e-6f) * inv_s;
        part2 = p0 * __log2f(p0) + p1 * __log2f(p1)
              + p2 * __log2f(p2) + p3 * __log2f(p3);
    }

    // per-chunk stable local ranks (16 warps, chunk = 256 pts, 8 rounds)
    if (wid < 16) {
        #pragma unroll 1
        for (int r = 0; r < 8; ++r) {
            int n = (wid << 8) + (r << 5) + lane;
            int v = scnt[n];
            unsigned peers = __match_any_sync(0xffffffffu, v);
            int lr = __popc(peers & ((1u << lane) - 1u));
            int base = chh[v * 17 + wid];
            lrk[n] = (unsigned short)(base + lr);
            if (lane == (__ffs(peers) - 1))
                chh[v * 17 + wid] = (unsigned short)(base + __popc(peers));
            __syncwarp();
        }
    }
    __syncthreads();

    // entropy reduction
    #pragma unroll
    for (int o = 16; o; o >>= 1) part2 += __shfl_down_sync(0xffffffffu, part2, o);
    if (lane == 0) red[wid] = part2;
    __syncthreads();
    if (wid == 0) {
        float v = red[lane];
        #pragma unroll
        for (int o = 16; o; o >>= 1) v += __shfl_down_sync(0xffffffffu, v, o);
        if (lane == 0) out_ent[b] = -v * (1.0f / 12.0f);   // log2(4096)=12
    }

    // per-value prefix across 16 chunks (thread t <-> value t)
    int tot;
    {
        int run = 0;
        #pragma unroll
        for (int w = 0; w < 16; ++w) {
            int cc = chh[t * 17 + w];
            chh[t * 17 + w] = (unsigned short)run;
            run += cc;
        }
        tot = run;
        if (t == 0) {    // value 1024
            int r2 = 0;
            #pragma unroll
            for (int w = 0; w < 16; ++w) {
                int cc = chh[1024 * 17 + w];
                chh[1024 * 17 + w] = (unsigned short)r2;
                r2 += cc;
            }
            gstart[1024] = 4096 - r2;
        }
    }

    // parallel exclusive scan of value totals (0..1023)
    int incl = tot;
    #pragma unroll
    for (int o = 1; o < 32; o <<= 1) {
        int u = __shfl_up_sync(0xffffffffu, incl, o);
        if (lane >= o) incl += u;
    }
    if (lane == 31) ired[wid] = incl;
    __syncthreads();
    if (wid == 0) {
        int v = ired[lane];
        int sc = v;
        #pragma unroll
        for (int o = 1; o < 32; o <<= 1) {
            int u = __shfl_up_sync(0xffffffffu, sc, o);
            if (lane >= o) sc += u;
        }
        ired[lane] = sc - v;
    }
    __syncthreads();
    gstart[t] = incl - tot + ired[wid];
    __syncthreads();

    // scatter final ranks
    #pragma unroll
    for (int n = t; n < NPTS; n += 1024) {
        int v = scnt[n];
        int rank = gstart[v] + (int)chh[v * 17 + (n >> 8)] + (int)lrk[n];
        out_imp2[(size_t)b * NPTS + rank] = (float)n;
    }
}

// ---------------------------------------------------------------------------
extern "C" void kernel_launch(void* const* d_in, const int* in_sizes, int n_in,
                              void* d_out, int out_size)
{
    const float* x = (const float*)d_in[0];   // [32, 3, 4096]
    const float* W = (const float*)d_in[1];   // [1024, 3]
    float* out = (float*)d_out;

    float* out_x      = out;
    float* out_counts = out + B_ * 3 * NPTS;
    float* out_imp2   = out_counts + B_ * NPTS;
    float* out_ent    = out_imp2 + B_ * NPTS;

    const int SORT_SMEM = 63552;
    cudaFuncSetAttribute(sort_entropy_kernel,
                         cudaFuncAttributeMaxDynamicSharedMemorySize, SORT_SMEM);

    prep_kernel<<<B_, 1024>>>(x, out_x);
    argmax_kernel<<<B_ * 4, 256>>>(W);
    sort_entropy_kernel<<<B_, 1024, SORT_SMEM>>>(out_counts, out_imp2, out_ent);
}

// round 9
// speedup vs baseline: 1.7232x; 1.7232x over previous
#include <cuda_runtime.h>
#include <math.h>

#define B_    32
#define NCH   1024
#define NPTS  4096
#define NBK   256        // radius buckets
#define NCHK  128        // 32-pt chunks per batch

__device__ int    g_imp[B_ * NCH];       // winner per (b, c)
__device__ float4 g_sorted[B_ * NPTS];   // (x,y,z, idx_bits) desc-radius order
__device__ float  g_chunkub[B_ * NCHK];  // radius upper bound per 32-pt chunk

typedef unsigned long long ull;

__device__ __forceinline__ unsigned int ordf(float f) {
    unsigned int u = __float_as_uint(f);
    return (u & 0x80000000u) ? ~u : (u | 0x80000000u);
}

// ---------------------------------------------------------------------------
// Kernel 0: per-batch prep. float4-vectorized radius + passthrough, bucket
// sort descending by radius, analytic chunk UBs from bucket edges.
// grid = 32, 1024 threads.
// ---------------------------------------------------------------------------
__global__ void __launch_bounds__(1024) prep_kernel(
    const float* __restrict__ x, float* __restrict__ out_x)
{
    __shared__ int hist[NBK];
    __shared__ int sbase[NBK];
    __shared__ int cur[NBK];
    __shared__ int ubi[NCHK];

    const int b    = blockIdx.x;
    const int t    = threadIdx.x;
    const int lane = t & 31;
    const int wid  = t >> 5;

    if (t < NBK) { hist[t] = 0; cur[t] = 0; }
    if (t < NCHK) ubi[t] = 0;
    __syncthreads();

    const float4* x0 = (const float4*)(x + (size_t)b * 3 * NPTS);
    const float4* x1 = x0 + NPTS / 4;
    const float4* x2 = x0 + NPTS / 2;
    float4*       o0 = (float4*)(out_x + (size_t)b * 3 * NPTS);

    float4 X = x0[t], Y = x1[t], Z = x2[t];
    o0[t] = X; o0[NPTS / 4 + t] = Y; o0[NPTS / 2 + t] = Z;   // passthrough

    float r_[4];
    int   bk[4];
    {
        float px[4] = {X.x, X.y, X.z, X.w};
        float py[4] = {Y.x, Y.y, Y.z, Y.w};
        float pz[4] = {Z.x, Z.y, Z.z, Z.w};
        #pragma unroll
        for (int k = 0; k < 4; ++k) {
            float r = __fsqrt_ru(__fmaf_rn(px[k], px[k],
                       __fmaf_rn(py[k], py[k], pz[k] * pz[k])));
            r_[k] = r;
            int bb = (int)(r * 40.0f);
            bk[k] = bb > 255 ? 255 : bb;
            atomicAdd(&hist[bk[k]], 1);
        }
    }
    __syncthreads();

    // exclusive offsets in DESCENDING bucket order (warp 0)
    if (wid == 0) {
        int carry = 0;
        #pragma unroll
        for (int seg = 0; seg < 8; ++seg) {
            int idx = 255 - (seg * 32 + lane);
            int v = hist[idx];
            int s = v;
            #pragma unroll
            for (int off = 1; off < 32; off <<= 1) {
                int u = __shfl_up_sync(0xffffffffu, s, off);
                if (lane >= off) s += u;
            }
            sbase[idx] = s - v + carry;
            carry += __shfl_sync(0xffffffffu, s, 31);
        }
    }
    __syncthreads();

    // scatter (order within bucket arbitrary); idx stored as raw bits in .w
    {
        float px[4] = {X.x, X.y, X.z, X.w};
        float py[4] = {Y.x, Y.y, Y.z, Y.w};
        float pz[4] = {Z.x, Z.y, Z.z, Z.w};
        #pragma unroll
        for (int k = 0; k < 4; ++k) {
            int p = t * 4 + k;
            int pos = sbase[bk[k]] + atomicAdd(&cur[bk[k]], 1);
            g_sorted[(size_t)b * NPTS + pos] =
                make_float4(px[k], py[k], pz[k], __uint_as_float((unsigned)p));
        }
    }

    // analytic chunk UBs: bucket bb's edge bounds its span's chunks; since
    // buckets are laid out descending, cub[ck] >= r of every point in chunks
    // >= ck automatically.
    if (t < NBK) {
        int s = sbase[t], h = hist[t];
        if (h > 0) {
            float edge = (t == 255) ? 3.0e38f : (float)(t + 1) * 0.025f * 1.001f;
            int c0 = s >> 5, c1 = (s + h - 1) >> 5;
            for (int c = c0; c <= c1; ++c)
                atomicMax(&ubi[c], __float_as_int(edge));   // nonneg floats: int max ok
        }
    }
    __syncthreads();
    if (t < NCHK) g_chunkub[b * NCHK + t] = __int_as_float(ubi[t]);
}

// ---------------------------------------------------------------------------
// Kernel 1: pruned argmax. WARP = one channel, lanes = 32 points/chunk.
// Scans descending-radius chunks; warp-uniform exit when chunk UB can no
// longer beat-or-tie the channel best. Exact fp32 argmax w/ first-index ties.
// grid = 4096 (32 b x 128), 256 threads (8 warps = 8 channels).
// ---------------------------------------------------------------------------
__global__ void __launch_bounds__(256) argmax_kernel(const float* __restrict__ W)
{
    __shared__ float cub[NCHK];

    const int b    = blockIdx.x >> 7;
    const int loc  = blockIdx.x & 127;
    const int lane = threadIdx.x & 31;
    const int wid  = threadIdx.x >> 5;
    const int c    = loc * 8 + wid;

    if (threadIdx.x < NCHK) cub[threadIdx.x] = g_chunkub[b * NCHK + threadIdx.x];
    __syncthreads();

    const float w0 = W[c * 3 + 0];
    const float w1 = W[c * 3 + 1];
    const float w2 = W[c * 3 + 2];
    const float wn = __fsqrt_ru(__fmaf_ru(w0, w0,
                      __fmaf_ru(w1, w1, __fmul_ru(w2, w2)))) * 1.00002f;

    const float4* sp = g_sorted + (size_t)b * NPTS;

    unsigned bestu = 0;          // warp-uniform ordf(best)
    ull      kbest = 0;          // per-lane (ordf(f)<<32)|(4095-idx)

    #pragma unroll 1
    for (int ck = 0; ck < NCHK; ++ck) {
        float4 p = sp[(ck << 5) + lane];            // coalesced 512B
        float f = __fmaf_rn(w2, p.z, __fmaf_rn(w1, p.y, __fmul_rn(w0, p.x)));
        unsigned k32 = ordf(f);
        unsigned idx = __float_as_uint(p.w);
        ull key = ((ull)k32 << 32) | (ull)(4095u - idx);
        kbest = kbest > key ? kbest : key;

        unsigned m = __reduce_max_sync(0xffffffffu, k32);
        bestu = bestu > m ? bestu : m;

        if (ck + 1 < NCHK) {
            if (ordf(cub[ck + 1] * wn) < bestu) break;   // no remaining beat/tie
        }
    }

    // warp argmax reduce (key max = max f, then min idx)
    #pragma unroll
    for (int o = 16; o; o >>= 1) {
        ull other = __shfl_xor_sync(0xffffffffu, kbest, o);
        kbest = kbest > other ? kbest : other;
    }
    if (lane == 0)
        g_imp[b * NCH + c] = 4095 - (int)(kbest & 0xFFFu);
}

// ---------------------------------------------------------------------------
// Kernel 2: counts, entropy, parallel stable counting sort (unchanged, proven).
// grid = 32, 1024 threads, 63.5KB dynamic smem.
// ---------------------------------------------------------------------------
__global__ void __launch_bounds__(1024) sort_entropy_kernel(
    float* __restrict__ out_counts,
    float* __restrict__ out_imp2,
    float* __restrict__ out_ent)
{
    extern __shared__ __align__(16) char smem_raw[];
    int*            scnt   = (int*)smem_raw;
    int*            gstart = (int*)(smem_raw + 16384);
    unsigned short* chh    = (unsigned short*)(smem_raw + 20488);  // 1025*17 u16
    unsigned short* lrk    = (unsigned short*)(smem_raw + 55340);  // 4096 u16
    __shared__ float red[32];
    __shared__ int   ired[32];

    const int b    = blockIdx.x;
    const int t    = threadIdx.x;
    const int lane = t & 31;
    const int wid  = t >> 5;

    const int myimp = g_imp[b * NCH + t];   // prefetch before zeroing

    #pragma unroll
    for (int i = t; i < NPTS; i += 1024) scnt[i] = 0;
    for (int i = t; i < 8713; i += 1024) ((unsigned*)chh)[i] = 0;
    __syncthreads();

    atomicAdd(&scnt[myimp], 1);
    __syncthreads();

    const float inv_s = 1.0f / (1024.0f + 4096.0f * 1e-6f);
    float part2;
    {
        int4 cv = ((const int4*)scnt)[t];
        float4 cf = make_float4((float)cv.x, (float)cv.y, (float)cv.z, (float)cv.w);
        ((float4*)(out_counts + (size_t)b * NPTS))[t] = cf;
        float p0 = (cf.x + 1e-6f) * inv_s, p1 = (cf.y + 1e-6f) * inv_s;
        float p2 = (cf.z + 1e-6f) * inv_s, p3 = (cf.w + 1e-6f) * inv_s;
        part2 = p0 * __log2f(p0) + p1 * __log2f(p1)
              + p2 * __log2f(p2) + p3 * __log2f(p3);
    }

    if (wid < 16) {
        #pragma unroll 1
        for (int r = 0; r < 8; ++r) {
            int n = (wid << 8) + (r << 5) + lane;
            int v = scnt[n];
            unsigned peers = __match_any_sync(0xffffffffu, v);
            int lr = __popc(peers & ((1u << lane) - 1u));
            int base = chh[v * 17 + wid];
            lrk[n] = (unsigned short)(base + lr);
            if (lane == (__ffs(peers) - 1))
                chh[v * 17 + wid] = (unsigned short)(base + __popc(peers));
            __syncwarp();
        }
    }
    __syncthreads();

    #pragma unroll
    for (int o = 16; o; o >>= 1) part2 += __shfl_down_sync(0xffffffffu, part2, o);
    if (lane == 0) red[wid] = part2;
    __syncthreads();
    if (wid == 0) {
        float v = red[lane];
        #pragma unroll
        for (int o = 16; o; o >>= 1) v += __shfl_down_sync(0xffffffffu, v, o);
        if (lane == 0) out_ent[b] = -v * (1.0f / 12.0f);   // log2(4096)=12
    }

    int tot;
    {
        int run = 0;
        #pragma unroll
        for (int w = 0; w < 16; ++w) {
            int cc = chh[t * 17 + w];
            chh[t * 17 + w] = (unsigned short)run;
            run += cc;
        }
        tot = run;
        if (t == 0) {
            int r2 = 0;
            #pragma unroll
            for (int w = 0; w < 16; ++w) {
                int cc = chh[1024 * 17 + w];
                chh[1024 * 17 + w] = (unsigned short)r2;
                r2 += cc;
            }
            gstart[1024] = 4096 - r2;
        }
    }

    int incl = tot;
    #pragma unroll
    for (int o = 1; o < 32; o <<= 1) {
        int u = __shfl_up_sync(0xffffffffu, incl, o);
        if (lane >= o) incl += u;
    }
    if (lane == 31) ired[wid] = incl;
    __syncthreads();
    if (wid == 0) {
        int v = ired[lane];
        int sc = v;
        #pragma unroll
        for (int o = 1; o < 32; o <<= 1) {
            int u = __shfl_up_sync(0xffffffffu, sc, o);
            if (lane >= o) sc += u;
        }
        ired[lane] = sc - v;
    }
    __syncthreads();
    gstart[t] = incl - tot + ired[wid];
    __syncthreads();

    #pragma unroll
    for (int n = t; n < NPTS; n += 1024) {
        int v = scnt[n];
        int rank = gstart[v] + (int)chh[v * 17 + (n >> 8)] + (int)lrk[n];
        out_imp2[(size_t)b * NPTS + rank] = (float)n;
    }
}

// ---------------------------------------------------------------------------
extern "C" void kernel_launch(void* const* d_in, const int* in_sizes, int n_in,
                              void* d_out, int out_size)
{
    const float* x = (const float*)d_in[0];   // [32, 3, 4096]
    const float* W = (const float*)d_in[1];   // [1024, 3]
    float* out = (float*)d_out;

    float* out_x      = out;
    float* out_counts = out + B_ * 3 * NPTS;
    float* out_imp2   = out_counts + B_ * NPTS;
    float* out_ent    = out_imp2 + B_ * NPTS;

    const int SORT_SMEM = 63552;
    cudaFuncSetAttribute(sort_entropy_kernel,
                         cudaFuncAttributeMaxDynamicSharedMemorySize, SORT_SMEM);

    prep_kernel<<<B_, 1024>>>(x, out_x);
    argmax_kernel<<<B_ * 128, 256>>>(W);
    sort_entropy_kernel<<<B_, 1024, SORT_SMEM>>>(out_counts, out_imp2, out_ent);
}